// round 12
// baseline (speedup 1.0000x reference)
#include <cuda_runtime.h>
#include <cuda_fp16.h>
#include <math.h>
#include <stdint.h>

#define NB     4
#define CH     512
#define LSEQ   2048
#define NHEADS 8
#define DHEAD  64
#define QKV_CH 1536
#define MROWS  (NB * LSEQ)          // 8192 flattened rows
#define QSCALE 0.18033688f          /* 0.125 * log2(e) */

// ---------------------------------------------------------------------------
// Scratch (no cudaMalloc allowed)
// ---------------------------------------------------------------------------
__device__ __half g_xsw  [(size_t)8 * MROWS * 64];      // x^T slab-major SW128
__device__ __half g_wqsw [(size_t)8 * QKV_CH * 64];     // w_qkv slab-major SW128
__device__ __half g_qkvT [(size_t)NB * LSEQ * QKV_CH];  // qkv^T [n][L][1536]
__device__ __half g_atth [(size_t)NB * LSEQ * CH];      // att^T [n][L][512]
__device__ __half g_wouth[CH * CH];                     // w_out row-major half

// ---------------------------------------------------------------------------
// helpers
// ---------------------------------------------------------------------------
__device__ __forceinline__ float ex2(float x) {
    float r; asm("ex2.approx.f32 %0, %1;" : "=f"(r) : "f"(x)); return r;
}
__device__ __forceinline__ uint32_t h2pack(float x, float y) {
    __half2 h = __floats2half2_rn(x, y);
    return *(uint32_t*)&h;
}
__device__ __forceinline__ void mma_f16(float c[4],
    uint32_t a0, uint32_t a1, uint32_t a2, uint32_t a3,
    uint32_t b0, uint32_t b1)
{
    asm volatile(
        "mma.sync.aligned.m16n8k16.row.col.f32.f16.f16.f32 "
        "{%0,%1,%2,%3}, {%4,%5,%6,%7}, {%8,%9}, {%0,%1,%2,%3};"
        : "+f"(c[0]), "+f"(c[1]), "+f"(c[2]), "+f"(c[3])
        : "r"(a0), "r"(a1), "r"(a2), "r"(a3), "r"(b0), "r"(b1));
}
__device__ __forceinline__ void ldsm4(uint32_t r[4], uint32_t addr) {
    asm volatile("ldmatrix.sync.aligned.m8n8.x4.shared.b16 {%0,%1,%2,%3}, [%4];"
        : "=r"(r[0]), "=r"(r[1]), "=r"(r[2]), "=r"(r[3]) : "r"(addr));
}
__device__ __forceinline__ void ldsm4t(uint32_t r[4], uint32_t addr) {
    asm volatile("ldmatrix.sync.aligned.m8n8.x4.trans.shared.b16 {%0,%1,%2,%3}, [%4];"
        : "=r"(r[0]), "=r"(r[1]), "=r"(r[2]), "=r"(r[3]) : "r"(addr));
}
__device__ __forceinline__ void cp128(uint32_t dst, const void* src) {
    asm volatile("cp.async.cg.shared.global [%0], [%1], 16;" :: "r"(dst), "l"(src));
}
#define CP_COMMIT() asm volatile("cp.async.commit_group;")
#define CP_WAIT(N)  asm volatile("cp.async.wait_group %0;" :: "n"(N))

__device__ __forceinline__ void bulk_g2s(uint32_t dst, const void* src,
                                         uint32_t bytes, uint32_t mbar)
{
    asm volatile(
        "cp.async.bulk.shared::cluster.global.mbarrier::complete_tx::bytes "
        "[%0], [%1], %2, [%3];"
        :: "r"(dst), "l"(src), "r"(bytes), "r"(mbar) : "memory");
}
__device__ __forceinline__ void mbar_expect(uint32_t mbar, uint32_t bytes) {
    asm volatile("mbarrier.arrive.expect_tx.shared.b64 _, [%0], %1;"
                 :: "r"(mbar), "r"(bytes) : "memory");
}
__device__ __forceinline__ void mbar_wait(uint32_t mbar, uint32_t parity) {
    asm volatile(
        "{\n\t.reg .pred P;\n\t"
        "LAB%=:\n\t"
        "mbarrier.try_wait.parity.acquire.cta.shared::cta.b64 P, [%0], %1;\n\t"
        "@!P bra LAB%=;\n\t"
        "}"
        :: "r"(mbar), "r"(parity) : "memory");
}

// ---------------------------------------------------------------------------
// prep: x -> slab-major SW128 half; w_qkv -> slab-major SW128 half;
// w_out -> plain half
// ---------------------------------------------------------------------------
__global__ void conv_half(const float4* __restrict__ in, __half2* __restrict__ out, int n4)
{
    int i = blockIdx.x * blockDim.x + threadIdx.x;
    if (i < n4) {
        float4 v = in[i];
        out[2 * i]     = __floats2half2_rn(v.x, v.y);
        out[2 * i + 1] = __floats2half2_rn(v.z, v.w);
    }
}

// x [NB][512][2048] float -> out [8][8192][64] half, SW128 within 128B rows
__global__ void x_to_slabsw(const float* __restrict__ in, __half* __restrict__ out)
{
    __shared__ float tile[32][33];
    const int n  = blockIdx.z;
    const int c0 = blockIdx.y * 32;
    const int l0 = blockIdx.x * 32;
    const int tx = threadIdx.x, ty = threadIdx.y;
    const float* src = in + (size_t)n * CH * LSEQ;
#pragma unroll
    for (int r = 0; r < 32; r += 8)
        tile[ty + r][tx] = src[(size_t)(c0 + ty + r) * LSEQ + l0 + tx];   // tile[c][l]
    __syncthreads();
#pragma unroll
    for (int r = 0; r < 32; r += 8) {
        const int l = l0 + ty + r;
        const int c = c0 + tx;
        const int m = n * LSEQ + l;
        const int slab = c >> 6, ck = c & 63;
        const int chunk = ck >> 3, wi = ck & 7;
        out[(size_t)slab * MROWS * 64 + (size_t)m * 64
            + ((chunk ^ (m & 7)) << 3) + wi] = __float2half(tile[tx][ty + r]);
    }
}

// w [M][512] float -> out [8][M][64] half, SW128 within rows
__global__ void w_to_slabsw(const float* __restrict__ in, __half* __restrict__ out, int M)
{
    const int idx = blockIdx.x * blockDim.x + threadIdx.x;
    if (idx >= M * CH) return;
    const int m = idx >> 9, k = idx & 511;
    const int slab = k >> 6, ck = k & 63;
    const int chunk = ck >> 3, wi = ck & 7;
    out[(size_t)slab * M * 64 + (size_t)m * 64
        + ((chunk ^ (m & 7)) << 3) + wi] = __float2half(in[idx]);
}

// ---------------------------------------------------------------------------
// QKV GEMM with cp.async.bulk staging.
// C[8192][1536] = A[8192][512] @ B[1536][512]^T, inputs slab-major SW128.
// CTA tile 256x128, 256 threads, 8 warps (4m x 2n), warp tile 64x64,
// 8 k-slabs of 64, 3-stage bulk pipeline (2 UBLKCP + 1 mbarrier per slab).
// ---------------------------------------------------------------------------
#define QA_BYTES 32768               // 256 rows x 128B
#define QB_BYTES 16384               // 128 rows x 128B
#define QSTG     (QA_BYTES + QB_BYTES)
#define QKV_SMEM (1024 + 3 * QSTG)   // 148480

__global__ __launch_bounds__(256, 1)
void gemm_qkv(const __half* __restrict__ Asw, const __half* __restrict__ Wsw,
              __half* __restrict__ Ch)
{
    extern __shared__ __half gsm[];
    const uint32_t base = (uint32_t)__cvta_generic_to_shared(gsm);

    const int t    = threadIdx.x;
    const int lane = t & 31;
    const int w    = t >> 5;
    const int qr   = lane >> 2;
    const int qc   = lane & 3;
    const int bm   = blockIdx.y * 256;
    const int bn   = blockIdx.x * 128;

    const int wm = (w >> 1) * 64;
    const int wn = (w & 1) * 64;

    // mbarriers at base+0,8,16; tiles at base+1024
    if (t == 0) {
#pragma unroll
        for (int s = 0; s < 3; s++)
            asm volatile("mbarrier.init.shared.b64 [%0], %1;"
                         :: "r"(base + s * 8), "r"(1u) : "memory");
    }
    __syncthreads();

    auto stage = [&](int slab, int buf) {
        const uint32_t mbar = base + buf * 8;
        const uint32_t aDst = base + 1024 + buf * QSTG;
        const uint32_t bDst = aDst + QA_BYTES;
        mbar_expect(mbar, QSTG);
        bulk_g2s(aDst, Asw + (size_t)slab * MROWS * 64 + (size_t)bm * 64,
                 QA_BYTES, mbar);
        bulk_g2s(bDst, Wsw + (size_t)slab * QKV_CH * 64 + (size_t)bn * 64,
                 QB_BYTES, mbar);
    };

    if (t == 0) { stage(0, 0); stage(1, 1); }

    float acc[4][8][4];
#pragma unroll
    for (int i = 0; i < 4; i++)
#pragma unroll
        for (int j = 0; j < 8; j++)
#pragma unroll
            for (int r = 0; r < 4; r++) acc[i][j][r] = 0.0f;

    const int nslabs = CH / 64;   // 8
    for (int i = 0; i < nslabs; i++) {
        __syncthreads();   // readers of slab i-1 (buffer (i+2)%3) are done
        if (t == 0 && i + 2 < nslabs) stage(i + 2, (i + 2) % 3);
        mbar_wait(base + (i % 3) * 8, (uint32_t)((i / 3) & 1));

        const uint32_t aS = base + 1024 + (i % 3) * QSTG;
        const uint32_t bS = aS + QA_BYTES;

#pragma unroll
        for (int kk = 0; kk < 4; kk++) {
            const int chA = kk * 2 + (lane >> 4);         // logical 16B chunk 0..7
            const int chB = kk * 2 + ((lane >> 3) & 1);
            uint32_t af[4][4];
#pragma unroll
            for (int mf = 0; mf < 4; mf++) {
                const int mi = wm + mf * 16 + (lane & 15);
                ldsm4(af[mf], aS + (uint32_t)(mi * 128 + ((chA ^ (mi & 7)) << 4)));
            }
            uint32_t bf[8][2];
#pragma unroll
            for (int np = 0; np < 4; np++) {
                uint32_t r[4];
                const int rb = wn + np * 16 + ((lane >> 4) << 3) + (lane & 7);
                ldsm4(r, bS + (uint32_t)(rb * 128 + ((chB ^ (rb & 7)) << 4)));
                bf[2 * np][0] = r[0]; bf[2 * np][1] = r[1];
                bf[2 * np + 1][0] = r[2]; bf[2 * np + 1][1] = r[3];
            }
#pragma unroll
            for (int nf = 0; nf < 8; nf++)
#pragma unroll
                for (int mf = 0; mf < 4; mf++)
                    mma_f16(acc[mf][nf], af[mf][0], af[mf][1], af[mf][2], af[mf][3],
                            bf[nf][0], bf[nf][1]);
        }
    }

    // epilogue: half2 coalesced into qkvT (row-major [8192][1536])
#pragma unroll
    for (int mf = 0; mf < 4; mf++) {
        const int row = bm + wm + mf * 16 + qr;
#pragma unroll
        for (int nf = 0; nf < 8; nf++) {
            const int col = bn + wn + nf * 8 + qc * 2;
            *(uint32_t*)(Ch + (size_t)row * QKV_CH + col) =
                h2pack(acc[mf][nf][0], acc[mf][nf][1]);
            *(uint32_t*)(Ch + (size_t)(row + 8) * QKV_CH + col) =
                h2pack(acc[mf][nf][2], acc[mf][nf][3]);
        }
    }
}

// ---------------------------------------------------------------------------
// Output-projection GEMM (round-11, unchanged): C = A @ B^T, 128x128 block,
// 256 threads, 8 warps (2m x 4n), warp tile 64x32, k-step 64, 3-stage cp.async.
// ---------------------------------------------------------------------------
#define GSW    72
#define GSTG   (128 * GSW)
#define G_SMEM (2 * 3 * GSTG * 2)

__global__ __launch_bounds__(256, 2)
void gemm_h(const __half* __restrict__ A, const __half* __restrict__ B,
            long strideA, long strideB,
            float* __restrict__ Cf, long strideCf, const float* __restrict__ bias,
            int ldc)
{
    extern __shared__ __half gsm[];
    __half* Asm = gsm;
    __half* Bsm = gsm + 3 * GSTG;

    const int t    = threadIdx.x;
    const int lane = t & 31;
    const int w    = t >> 5;
    const int qr   = lane >> 2;
    const int qc   = lane & 3;
    const int bm   = blockIdx.y * 128;
    const int bn   = blockIdx.x * 128;
    const int z    = blockIdx.z;

    A += (size_t)z * strideA;
    B += (size_t)z * strideB;

    const int wm = (w >> 2) * 64;
    const int wn = (w & 3) * 32;

    const uint32_t aBase = (uint32_t)__cvta_generic_to_shared(Asm);
    const uint32_t bBase = (uint32_t)__cvta_generic_to_shared(Bsm);

    const int srow = t & 127;
    auto stage = [&](int slab, int buf) {
        const __half* src = (t < 128)
            ? A + (size_t)(bm + srow) * CH + slab * 64
            : B + (size_t)(bn + srow) * CH + slab * 64;
        uint32_t dst = ((t < 128) ? aBase : bBase)
                     + (uint32_t)((buf * GSTG + srow * GSW) * 2);
#pragma unroll
        for (int c = 0; c < 8; c++)
            cp128(dst + c * 16, src + c * 8);
    };

    float acc[4][4][4];
#pragma unroll
    for (int i = 0; i < 4; i++)
#pragma unroll
        for (int j = 0; j < 4; j++)
#pragma unroll
            for (int r = 0; r < 4; r++) acc[i][j][r] = 0.0f;

    stage(0, 0); CP_COMMIT();
    stage(1, 1); CP_COMMIT();

    const int nslabs = CH / 64;
    for (int i = 0; i < nslabs; i++) {
        const int s = i % 3;
        if (i + 2 < nslabs) { stage(i + 2, (i + 2) % 3); CP_COMMIT(); CP_WAIT(2); }
        else if (i + 1 < nslabs) { CP_WAIT(1); }
        else { CP_WAIT(0); }
        __syncthreads();

        const uint32_t aS = aBase + (uint32_t)(s * GSTG * 2);
        const uint32_t bS = bBase + (uint32_t)(s * GSTG * 2);

#pragma unroll
        for (int kk = 0; kk < 4; kk++) {
            const int kc  = kk * 16 + (lane >> 4) * 8;
            const int bkc = kk * 16 + ((lane >> 3) & 1) * 8;
            uint32_t af[4][4];
#pragma unroll
            for (int mf = 0; mf < 4; mf++)
                ldsm4(af[mf], aS + (uint32_t)(((wm + mf * 16 + (lane & 15)) * GSW + kc) * 2));
            uint32_t bf[4][2];
#pragma unroll
            for (int np = 0; np < 2; np++) {
                uint32_t r[4];
                const int row = wn + np * 16 + ((lane >> 4) << 3) + (lane & 7);
                ldsm4(r, bS + (uint32_t)((row * GSW + bkc) * 2));
                bf[2 * np][0] = r[0]; bf[2 * np][1] = r[1];
                bf[2 * np + 1][0] = r[2]; bf[2 * np + 1][1] = r[3];
            }
#pragma unroll
            for (int nf = 0; nf < 4; nf++)
#pragma unroll
                for (int mf = 0; mf < 4; mf++)
                    mma_f16(acc[mf][nf], af[mf][0], af[mf][1], af[mf][2], af[mf][3],
                            bf[nf][0], bf[nf][1]);
        }
        __syncthreads();
    }

    Cf += (size_t)z * strideCf;
#pragma unroll
    for (int mf = 0; mf < 4; mf++) {
        const int row = bm + wm + mf * 16 + qr;
        const float bv0 = bias[row], bv1 = bias[row + 8];
#pragma unroll
        for (int nf = 0; nf < 4; nf++) {
            const int col = bn + wn + nf * 8 + qc * 2;
            *(float2*)(Cf + (size_t)row * ldc + col) =
                make_float2(acc[mf][nf][0] + bv0, acc[mf][nf][1] + bv0);
            *(float2*)(Cf + (size_t)(row + 8) * ldc + col) =
                make_float2(acc[mf][nf][2] + bv1, acc[mf][nf][3] + bv1);
        }
    }
}

// ---------------------------------------------------------------------------
// fp16 flash attention (round-9, unchanged): no-max base-2 softmax,
// Bq=256, 256 threads, 8 warps x m32n64, Bk=64, mma.sync.
// ---------------------------------------------------------------------------
#define QSW       72
#define QS_HALFS  (256 * QSW)
#define KSW       72
#define KS_HALFS  (64 * KSW)
#define FL_SMEM   ((QS_HALFS + 4 * KS_HALFS) * 2)   // 73728 bytes

__global__ __launch_bounds__(256, 1)
void flash_h(const __half* __restrict__ qkvT, __half* __restrict__ atth)
{
    extern __shared__ __half fsm[];
    const uint32_t qsBase = (uint32_t)__cvta_generic_to_shared(fsm);
    const uint32_t ksBase = qsBase + QS_HALFS * 2;
    const uint32_t vsBase = ksBase + 2 * KS_HALFS * 2;

    const int t    = threadIdx.x;
    const int lane = t & 31;
    const int w    = t >> 5;
    const int qr   = lane >> 2;
    const int qc   = lane & 3;
    const int i0   = blockIdx.x * 256;
    const int nh   = blockIdx.y;
    const int n    = nh >> 3, h = nh & 7;

    qkvT += (size_t)n * LSEQ * QKV_CH;
    atth += (size_t)n * LSEQ * CH;

    const int sr = t >> 2;
    const int sq = t & 3;

    auto stageKV = [&](int jt, int buf) {
        const __half* ksrc = qkvT + (size_t)(jt * 64 + sr) * QKV_CH + 512 + h * 64;
        const __half* vsrc = qkvT + (size_t)(jt * 64 + sr) * QKV_CH + 1024 + h * 64;
        uint32_t kdst = ksBase + (uint32_t)((buf * KS_HALFS + sr * KSW) * 2);
        uint32_t vdst = vsBase + (uint32_t)((buf * KS_HALFS + sr * KSW) * 2);
#pragma unroll
        for (int c = 0; c < 2; c++) {
            const int ch = sq + 4 * c;
            cp128(kdst + ch * 16, ksrc + ch * 8);
            cp128(vdst + ch * 16, vsrc + ch * 8);
        }
    };

    stageKV(0, 0); CP_COMMIT();
    {
        const __half* qsrc = qkvT + (size_t)(i0 + t) * QKV_CH + h * 64;
        uint32_t qdst = qsBase + (uint32_t)(t * QSW * 2);
#pragma unroll
        for (int c = 0; c < 8; c++)
            cp128(qdst + c * 16, qsrc + c * 8);
    }
    CP_COMMIT();
    CP_WAIT(0);
    __syncthreads();

    uint32_t qf[2][4][4];
    {
        const __half2 qs2 = __floats2half2_rn(QSCALE, QSCALE);
#pragma unroll
        for (int mf = 0; mf < 2; mf++)
#pragma unroll
            for (int kk = 0; kk < 4; kk++) {
                const int row = w * 32 + mf * 16 + (lane & 15);
                const int col = kk * 16 + (lane >> 4) * 8;
                ldsm4(qf[mf][kk], qsBase + (uint32_t)((row * QSW + col) * 2));
#pragma unroll
                for (int r = 0; r < 4; r++) {
                    __half2 v = __hmul2(*(__half2*)&qf[mf][kk][r], qs2);
                    qf[mf][kk][r] = *(uint32_t*)&v;
                }
            }
    }

    float lsum[2][2] = {{0.0f, 0.0f}, {0.0f, 0.0f}};
    float o[2][8][4];
#pragma unroll
    for (int mf = 0; mf < 2; mf++)
#pragma unroll
        for (int df = 0; df < 8; df++)
#pragma unroll
            for (int r = 0; r < 4; r++) o[mf][df][r] = 0.0f;

    const int njt = LSEQ / 64;
    for (int jt = 0; jt < njt; jt++) {
        const int s = jt & 1;
        if (jt + 1 < njt) { stageKV(jt + 1, s ^ 1); CP_COMMIT(); CP_WAIT(1); }
        else { CP_WAIT(0); }
        __syncthreads();

        float sreg[2][8][4];
#pragma unroll
        for (int mf = 0; mf < 2; mf++)
#pragma unroll
            for (int nf = 0; nf < 8; nf++)
#pragma unroll
                for (int r = 0; r < 4; r++) sreg[mf][nf][r] = 0.0f;

#pragma unroll
        for (int kk = 0; kk < 4; kk++) {
            const int bcol = kk * 16 + ((lane >> 3) & 1) * 8;
            uint32_t bf[8][2];
#pragma unroll
            for (int np = 0; np < 4; np++) {
                uint32_t r[4];
                const int row = np * 16 + ((lane >> 4) << 3) + (lane & 7);
                ldsm4(r, ksBase + (uint32_t)((s * KS_HALFS + row * KSW + bcol) * 2));
                bf[2 * np][0] = r[0]; bf[2 * np][1] = r[1];
                bf[2 * np + 1][0] = r[2]; bf[2 * np + 1][1] = r[3];
            }
#pragma unroll
            for (int nf = 0; nf < 8; nf++) {
                mma_f16(sreg[0][nf], qf[0][kk][0], qf[0][kk][1], qf[0][kk][2], qf[0][kk][3],
                        bf[nf][0], bf[nf][1]);
                mma_f16(sreg[1][nf], qf[1][kk][0], qf[1][kk][1], qf[1][kk][2], qf[1][kk][3],
                        bf[nf][0], bf[nf][1]);
            }
        }

        uint32_t pf[2][4][4];
#pragma unroll
        for (int mf = 0; mf < 2; mf++) {
#pragma unroll
            for (int nf = 0; nf < 8; nf++) {
                float p0 = ex2(sreg[mf][nf][0]);
                float p1 = ex2(sreg[mf][nf][1]);
                float p2 = ex2(sreg[mf][nf][2]);
                float p3 = ex2(sreg[mf][nf][3]);
                lsum[mf][0] += p0 + p1;
                lsum[mf][1] += p2 + p3;
                sreg[mf][nf][0] = p0; sreg[mf][nf][1] = p1;
                sreg[mf][nf][2] = p2; sreg[mf][nf][3] = p3;
            }
#pragma unroll
            for (int kk = 0; kk < 4; kk++) {
                pf[mf][kk][0] = h2pack(sreg[mf][2 * kk][0],     sreg[mf][2 * kk][1]);
                pf[mf][kk][1] = h2pack(sreg[mf][2 * kk][2],     sreg[mf][2 * kk][3]);
                pf[mf][kk][2] = h2pack(sreg[mf][2 * kk + 1][0], sreg[mf][2 * kk + 1][1]);
                pf[mf][kk][3] = h2pack(sreg[mf][2 * kk + 1][2], sreg[mf][2 * kk + 1][3]);
            }
        }

#pragma unroll
        for (int kk = 0; kk < 4; kk++) {
            uint32_t vf[8][2];
#pragma unroll
            for (int dp = 0; dp < 4; dp++) {
                uint32_t r[4];
                const int row = kk * 16 + (lane & 15);
                const int col = dp * 16 + (lane >> 4) * 8;
                ldsm4t(r, vsBase + (uint32_t)((s * KS_HALFS + row * KSW + col) * 2));
                vf[2 * dp][0] = r[0]; vf[2 * dp][1] = r[1];
                vf[2 * dp + 1][0] = r[2]; vf[2 * dp + 1][1] = r[3];
            }
#pragma unroll
            for (int df = 0; df < 8; df++) {
                mma_f16(o[0][df], pf[0][kk][0], pf[0][kk][1], pf[0][kk][2], pf[0][kk][3],
                        vf[df][0], vf[df][1]);
                mma_f16(o[1][df], pf[1][kk][0], pf[1][kk][1], pf[1][kk][2], pf[1][kk][3],
                        vf[df][0], vf[df][1]);
            }
        }
        __syncthreads();
    }

#pragma unroll
    for (int mf = 0; mf < 2; mf++) {
        float r0 = lsum[mf][0], r1 = lsum[mf][1];
        r0 += __shfl_xor_sync(0xffffffffu, r0, 1);
        r0 += __shfl_xor_sync(0xffffffffu, r0, 2);
        r1 += __shfl_xor_sync(0xffffffffu, r1, 1);
        r1 += __shfl_xor_sync(0xffffffffu, r1, 2);
        const float inv0 = 1.0f / r0, inv1 = 1.0f / r1;
        const int gi = i0 + w * 32 + mf * 16 + qr;
#pragma unroll
        for (int df = 0; df < 8; df++) {
            const int col = h * 64 + df * 8 + qc * 2;
            *(uint32_t*)(atth + (size_t)gi * CH + col) =
                h2pack(o[mf][df][0] * inv0, o[mf][df][1] * inv0);
            *(uint32_t*)(atth + (size_t)(gi + 8) * CH + col) =
                h2pack(o[mf][df][2] * inv1, o[mf][df][3] * inv1);
        }
    }
}

// ---------------------------------------------------------------------------
// Launch
// ---------------------------------------------------------------------------
extern "C" void kernel_launch(void* const* d_in, const int* in_sizes, int n_in,
                              void* d_out, int out_size)
{
    const float* x     = (const float*)d_in[0];
    const float* w_qkv = (const float*)d_in[1];
    const float* w_out = (const float*)d_in[2];
    const float* b_out = (const float*)d_in[3];
    float* out = (float*)d_out;

    __half *xsw, *wqsw, *qkvT, *atth, *woh;
    cudaGetSymbolAddress((void**)&xsw,  g_xsw);
    cudaGetSymbolAddress((void**)&wqsw, g_wqsw);
    cudaGetSymbolAddress((void**)&qkvT, g_qkvT);
    cudaGetSymbolAddress((void**)&atth, g_atth);
    cudaGetSymbolAddress((void**)&woh,  g_wouth);

    cudaFuncSetAttribute(gemm_qkv, cudaFuncAttributeMaxDynamicSharedMemorySize, QKV_SMEM);
    cudaFuncSetAttribute(gemm_h,   cudaFuncAttributeMaxDynamicSharedMemorySize, G_SMEM);
    cudaFuncSetAttribute(flash_h,  cudaFuncAttributeMaxDynamicSharedMemorySize, FL_SMEM);

    // prep
    x_to_slabsw<<<dim3(LSEQ / 32, CH / 32, NB), dim3(32, 8)>>>(x, xsw);
    w_to_slabsw<<<(QKV_CH * CH + 255) / 256, 256>>>(w_qkv, wqsw, QKV_CH);
    conv_half<<<(CH * CH / 4 + 255) / 256, 256>>>((const float4*)w_out, (__half2*)woh, CH * CH / 4);

    // 1) qkvT[(n,l)][o]  (bulk-staged GEMM)
    {
        dim3 grid(QKV_CH / 128, MROWS / 256);
        gemm_qkv<<<grid, 256, QKV_SMEM>>>(xsw, wqsw, qkvT);
    }
    // 2) flash attention -> atth [L][512] half
    {
        dim3 grid(LSEQ / 256, NB * NHEADS);
        flash_h<<<grid, 256, FL_SMEM>>>(qkvT, atth);
    }
    // 3) out[n][o][l] = w_out[o][:] . atth[n][l][:] + b_out
    {
        dim3 grid(LSEQ / 128, CH / 128, NB);
        gemm_h<<<grid, 256, G_SMEM>>>(woh, atth, 0L, (long)LSEQ * CH,
                                      out, (long)CH * LSEQ, b_out, LSEQ);
    }
}

// round 13
// speedup vs baseline: 1.6878x; 1.6878x over previous
#include <cuda_runtime.h>
#include <cuda_fp16.h>
#include <math.h>
#include <stdint.h>

#define NB     4
#define CH     512
#define LSEQ   2048
#define NHEADS 8
#define DHEAD  64
#define QKV_CH 1536
#define MROWS  (NB * LSEQ)          // 8192 flattened rows
#define QSCALE 0.18033688f          /* 0.125 * log2(e) */

// ---------------------------------------------------------------------------
// Scratch (no cudaMalloc allowed)
// ---------------------------------------------------------------------------
__device__ __half g_xsw  [(size_t)8 * MROWS * 64];      // x^T slab-major SW128
__device__ __half g_wqsw [(size_t)8 * QKV_CH * 64];     // w_qkv slab-major SW128
__device__ __half g_wosw [(size_t)8 * CH * 64];         // w_out slab-major SW128
__device__ __half g_qkvT [(size_t)MROWS * QKV_CH];      // qkv^T [m][1536]
__device__ __half g_attsw[(size_t)8 * MROWS * 64];      // att slab-major SW128 (slab=h)

// ---------------------------------------------------------------------------
// helpers
// ---------------------------------------------------------------------------
__device__ __forceinline__ float ex2(float x) {
    float r; asm("ex2.approx.f32 %0, %1;" : "=f"(r) : "f"(x)); return r;
}
__device__ __forceinline__ uint32_t h2pack(float x, float y) {
    __half2 h = __floats2half2_rn(x, y);
    return *(uint32_t*)&h;
}
__device__ __forceinline__ void mma_f16(float c[4],
    uint32_t a0, uint32_t a1, uint32_t a2, uint32_t a3,
    uint32_t b0, uint32_t b1)
{
    asm volatile(
        "mma.sync.aligned.m16n8k16.row.col.f32.f16.f16.f32 "
        "{%0,%1,%2,%3}, {%4,%5,%6,%7}, {%8,%9}, {%0,%1,%2,%3};"
        : "+f"(c[0]), "+f"(c[1]), "+f"(c[2]), "+f"(c[3])
        : "r"(a0), "r"(a1), "r"(a2), "r"(a3), "r"(b0), "r"(b1));
}
__device__ __forceinline__ void ldsm4(uint32_t r[4], uint32_t addr) {
    asm volatile("ldmatrix.sync.aligned.m8n8.x4.shared.b16 {%0,%1,%2,%3}, [%4];"
        : "=r"(r[0]), "=r"(r[1]), "=r"(r[2]), "=r"(r[3]) : "r"(addr));
}
__device__ __forceinline__ void ldsm4t(uint32_t r[4], uint32_t addr) {
    asm volatile("ldmatrix.sync.aligned.m8n8.x4.trans.shared.b16 {%0,%1,%2,%3}, [%4];"
        : "=r"(r[0]), "=r"(r[1]), "=r"(r[2]), "=r"(r[3]) : "r"(addr));
}
__device__ __forceinline__ void cp128(uint32_t dst, const void* src) {
    asm volatile("cp.async.cg.shared.global [%0], [%1], 16;" :: "r"(dst), "l"(src));
}
#define CP_COMMIT() asm volatile("cp.async.commit_group;")
#define CP_WAIT(N)  asm volatile("cp.async.wait_group %0;" :: "n"(N))

__device__ __forceinline__ void bulk_g2s(uint32_t dst, const void* src,
                                         uint32_t bytes, uint32_t mbar)
{
    asm volatile(
        "cp.async.bulk.shared::cluster.global.mbarrier::complete_tx::bytes "
        "[%0], [%1], %2, [%3];"
        :: "r"(dst), "l"(src), "r"(bytes), "r"(mbar) : "memory");
}
__device__ __forceinline__ void mbar_expect(uint32_t mbar, uint32_t bytes) {
    asm volatile("mbarrier.arrive.expect_tx.shared.b64 _, [%0], %1;"
                 :: "r"(mbar), "r"(bytes) : "memory");
}
__device__ __forceinline__ void mbar_wait(uint32_t mbar, uint32_t parity) {
    asm volatile(
        "{\n\t.reg .pred P;\n\t"
        "LAB%=:\n\t"
        "mbarrier.try_wait.parity.acquire.cta.shared::cta.b64 P, [%0], %1;\n\t"
        "@!P bra LAB%=;\n\t"
        "}"
        :: "r"(mbar), "r"(parity) : "memory");
}

// ---------------------------------------------------------------------------
// prep (vectorized): x -> slab-major SW128; weights -> slab-major SW128
// ---------------------------------------------------------------------------
// x [NB][512][2048] float -> out [8][8192][64] half, 16B-chunk stores
__global__ void x_to_slabsw(const float* __restrict__ in, __half* __restrict__ out)
{
    __shared__ float tile[64][33];
    const int n  = blockIdx.z;
    const int c0 = blockIdx.y * 64;       // one slab per block
    const int l0 = blockIdx.x * 32;
    const int t  = threadIdx.x;           // 256

    const float* src = in + (size_t)n * CH * LSEQ;
    {
        const int lx = t & 31, cy = t >> 5;   // cy 0..7
#pragma unroll
        for (int j = 0; j < 8; j++)
            tile[cy * 8 + j][lx] = src[(size_t)(c0 + cy * 8 + j) * LSEQ + l0 + lx];
    }
    __syncthreads();
    {
        const int chunk = t & 7, l = t >> 3;  // l 0..31
        const int m = n * LSEQ + l0 + l;
        __half h[8];
#pragma unroll
        for (int j = 0; j < 8; j++) h[j] = __float2half(tile[chunk * 8 + j][l]);
        const int slab = c0 >> 6;
        *(uint4*)&out[(size_t)slab * MROWS * 64 + (size_t)m * 64
                      + ((chunk ^ (m & 7)) << 3)] = *(uint4*)h;
    }
}

// w [M][512] float -> out [8][M][64] half, 16B-chunk stores
__global__ void w_to_slabsw(const float* __restrict__ in, __half* __restrict__ out, int M)
{
    const int idx = blockIdx.x * blockDim.x + threadIdx.x;   // chunk id
    if (idx >= M * 64) return;
    const int m = idx >> 6, kc = idx & 63;
    const int slab = kc >> 3, chunk = kc & 7;
    float4 f0 = *(const float4*)&in[(size_t)m * CH + kc * 8];
    float4 f1 = *(const float4*)&in[(size_t)m * CH + kc * 8 + 4];
    __half h[8];
    h[0] = __float2half(f0.x); h[1] = __float2half(f0.y);
    h[2] = __float2half(f0.z); h[3] = __float2half(f0.w);
    h[4] = __float2half(f1.x); h[5] = __float2half(f1.y);
    h[6] = __float2half(f1.z); h[7] = __float2half(f1.w);
    *(uint4*)&out[(size_t)slab * M * 64 + (size_t)m * 64
                  + ((chunk ^ (m & 7)) << 3)] = *(uint4*)h;
}

// ---------------------------------------------------------------------------
// QKV GEMM with cp.async.bulk staging (round-12, unchanged).
// C[8192][1536] = A[8192][512] @ B[1536][512]^T, inputs slab-major SW128.
// ---------------------------------------------------------------------------
#define QA_BYTES 32768
#define QB_BYTES 16384
#define QSTG     (QA_BYTES + QB_BYTES)
#define QKV_SMEM (1024 + 3 * QSTG)   // 148480

__global__ __launch_bounds__(256, 1)
void gemm_qkv(const __half* __restrict__ Asw, const __half* __restrict__ Wsw,
              __half* __restrict__ Ch)
{
    extern __shared__ __half gsm[];
    const uint32_t base = (uint32_t)__cvta_generic_to_shared(gsm);

    const int t    = threadIdx.x;
    const int lane = t & 31;
    const int w    = t >> 5;
    const int qr   = lane >> 2;
    const int qc   = lane & 3;
    const int bm   = blockIdx.y * 256;
    const int bn   = blockIdx.x * 128;

    const int wm = (w >> 1) * 64;
    const int wn = (w & 1) * 64;

    if (t == 0) {
#pragma unroll
        for (int s = 0; s < 3; s++)
            asm volatile("mbarrier.init.shared.b64 [%0], %1;"
                         :: "r"(base + s * 8), "r"(1u) : "memory");
    }
    __syncthreads();

    auto stage = [&](int slab, int buf) {
        const uint32_t mbar = base + buf * 8;
        const uint32_t aDst = base + 1024 + buf * QSTG;
        const uint32_t bDst = aDst + QA_BYTES;
        mbar_expect(mbar, QSTG);
        bulk_g2s(aDst, Asw + (size_t)slab * MROWS * 64 + (size_t)bm * 64,
                 QA_BYTES, mbar);
        bulk_g2s(bDst, Wsw + (size_t)slab * QKV_CH * 64 + (size_t)bn * 64,
                 QB_BYTES, mbar);
    };

    if (t == 0) { stage(0, 0); stage(1, 1); }

    float acc[4][8][4];
#pragma unroll
    for (int i = 0; i < 4; i++)
#pragma unroll
        for (int j = 0; j < 8; j++)
#pragma unroll
            for (int r = 0; r < 4; r++) acc[i][j][r] = 0.0f;

    const int nslabs = CH / 64;   // 8
    for (int i = 0; i < nslabs; i++) {
        __syncthreads();
        if (t == 0 && i + 2 < nslabs) stage(i + 2, (i + 2) % 3);
        mbar_wait(base + (i % 3) * 8, (uint32_t)((i / 3) & 1));

        const uint32_t aS = base + 1024 + (i % 3) * QSTG;
        const uint32_t bS = aS + QA_BYTES;

#pragma unroll
        for (int kk = 0; kk < 4; kk++) {
            const int chA = kk * 2 + (lane >> 4);
            const int chB = kk * 2 + ((lane >> 3) & 1);
            uint32_t af[4][4];
#pragma unroll
            for (int mf = 0; mf < 4; mf++) {
                const int mi = wm + mf * 16 + (lane & 15);
                ldsm4(af[mf], aS + (uint32_t)(mi * 128 + ((chA ^ (mi & 7)) << 4)));
            }
            uint32_t bf[8][2];
#pragma unroll
            for (int np = 0; np < 4; np++) {
                uint32_t r[4];
                const int rb = wn + np * 16 + ((lane >> 4) << 3) + (lane & 7);
                ldsm4(r, bS + (uint32_t)(rb * 128 + ((chB ^ (rb & 7)) << 4)));
                bf[2 * np][0] = r[0]; bf[2 * np][1] = r[1];
                bf[2 * np + 1][0] = r[2]; bf[2 * np + 1][1] = r[3];
            }
#pragma unroll
            for (int nf = 0; nf < 8; nf++)
#pragma unroll
                for (int mf = 0; mf < 4; mf++)
                    mma_f16(acc[mf][nf], af[mf][0], af[mf][1], af[mf][2], af[mf][3],
                            bf[nf][0], bf[nf][1]);
        }
    }

#pragma unroll
    for (int mf = 0; mf < 4; mf++) {
        const int row = bm + wm + mf * 16 + qr;
#pragma unroll
        for (int nf = 0; nf < 8; nf++) {
            const int col = bn + wn + nf * 8 + qc * 2;
            *(uint32_t*)(Ch + (size_t)row * QKV_CH + col) =
                h2pack(acc[mf][nf][0], acc[mf][nf][1]);
            *(uint32_t*)(Ch + (size_t)(row + 8) * QKV_CH + col) =
                h2pack(acc[mf][nf][2], acc[mf][nf][3]);
        }
    }
}

// ---------------------------------------------------------------------------
// Projection GEMM with bulk staging.
// out[n][o][l] = w_out[o][:] . att[(n,l)][:] + bias[o].
// A = w_out slab-SW [8][512][64]; B = attsw [8][8192][64]; tile 256(o) x 128(l).
// ---------------------------------------------------------------------------
__global__ __launch_bounds__(256, 1)
void gemm_proj(const __half* __restrict__ Wsw, const __half* __restrict__ Bsw,
               float* __restrict__ out, const float* __restrict__ bias)
{
    extern __shared__ __half gsm[];
    const uint32_t base = (uint32_t)__cvta_generic_to_shared(gsm);

    const int t    = threadIdx.x;
    const int lane = t & 31;
    const int w    = t >> 5;
    const int qr   = lane >> 2;
    const int qc   = lane & 3;
    const int bm   = blockIdx.y * 256;              // o
    const int bn   = blockIdx.x * 128;              // l
    const int n    = blockIdx.z;
    const int brow = n * LSEQ + bn;                 // global att row base

    const int wm = (w >> 1) * 64;
    const int wn = (w & 1) * 64;

    if (t == 0) {
#pragma unroll
        for (int s = 0; s < 3; s++)
            asm volatile("mbarrier.init.shared.b64 [%0], %1;"
                         :: "r"(base + s * 8), "r"(1u) : "memory");
    }
    __syncthreads();

    auto stage = [&](int slab, int buf) {
        const uint32_t mbar = base + buf * 8;
        const uint32_t aDst = base + 1024 + buf * QSTG;
        const uint32_t bDst = aDst + QA_BYTES;
        mbar_expect(mbar, QSTG);
        bulk_g2s(aDst, Wsw + (size_t)slab * CH * 64 + (size_t)bm * 64,
                 QA_BYTES, mbar);
        bulk_g2s(bDst, Bsw + (size_t)slab * MROWS * 64 + (size_t)brow * 64,
                 QB_BYTES, mbar);
    };

    if (t == 0) { stage(0, 0); stage(1, 1); }

    float acc[4][8][4];
#pragma unroll
    for (int i = 0; i < 4; i++)
#pragma unroll
        for (int j = 0; j < 8; j++)
#pragma unroll
            for (int r = 0; r < 4; r++) acc[i][j][r] = 0.0f;

    const int nslabs = CH / 64;
    for (int i = 0; i < nslabs; i++) {
        __syncthreads();
        if (t == 0 && i + 2 < nslabs) stage(i + 2, (i + 2) % 3);
        mbar_wait(base + (i % 3) * 8, (uint32_t)((i / 3) & 1));

        const uint32_t aS = base + 1024 + (i % 3) * QSTG;
        const uint32_t bS = aS + QA_BYTES;

#pragma unroll
        for (int kk = 0; kk < 4; kk++) {
            const int chA = kk * 2 + (lane >> 4);
            const int chB = kk * 2 + ((lane >> 3) & 1);
            uint32_t af[4][4];
#pragma unroll
            for (int mf = 0; mf < 4; mf++) {
                const int mi = wm + mf * 16 + (lane & 15);
                ldsm4(af[mf], aS + (uint32_t)(mi * 128 + ((chA ^ (mi & 7)) << 4)));
            }
            uint32_t bf[8][2];
#pragma unroll
            for (int np = 0; np < 4; np++) {
                uint32_t r[4];
                const int rb = wn + np * 16 + ((lane >> 4) << 3) + (lane & 7);
                ldsm4(r, bS + (uint32_t)(rb * 128 + ((chB ^ (rb & 7)) << 4)));
                bf[2 * np][0] = r[0]; bf[2 * np][1] = r[1];
                bf[2 * np + 1][0] = r[2]; bf[2 * np + 1][1] = r[3];
            }
#pragma unroll
            for (int nf = 0; nf < 8; nf++)
#pragma unroll
                for (int mf = 0; mf < 4; mf++)
                    mma_f16(acc[mf][nf], af[mf][0], af[mf][1], af[mf][2], af[mf][3],
                            bf[nf][0], bf[nf][1]);
        }
    }

    out += (size_t)n * CH * LSEQ;
#pragma unroll
    for (int mf = 0; mf < 4; mf++) {
        const int row = bm + wm + mf * 16 + qr;
        const float bv0 = bias[row], bv1 = bias[row + 8];
#pragma unroll
        for (int nf = 0; nf < 8; nf++) {
            const int col = bn + wn + nf * 8 + qc * 2;
            *(float2*)(out + (size_t)row * LSEQ + col) =
                make_float2(acc[mf][nf][0] + bv0, acc[mf][nf][1] + bv0);
            *(float2*)(out + (size_t)(row + 8) * LSEQ + col) =
                make_float2(acc[mf][nf][2] + bv1, acc[mf][nf][3] + bv1);
        }
    }
}

// ---------------------------------------------------------------------------
// fp16 flash attention (round-9 mainloop); epilogue writes attsw slab-major
// SW128 (slab = head, since each head spans exactly 64 channels).
// ---------------------------------------------------------------------------
#define QSW       72
#define QS_HALFS  (256 * QSW)
#define KSW       72
#define KS_HALFS  (64 * KSW)
#define FL_SMEM   ((QS_HALFS + 4 * KS_HALFS) * 2)   // 73728 bytes

__global__ __launch_bounds__(256, 1)
void flash_h(const __half* __restrict__ qkvT, __half* __restrict__ attsw)
{
    extern __shared__ __half fsm[];
    const uint32_t qsBase = (uint32_t)__cvta_generic_to_shared(fsm);
    const uint32_t ksBase = qsBase + QS_HALFS * 2;
    const uint32_t vsBase = ksBase + 2 * KS_HALFS * 2;

    const int t    = threadIdx.x;
    const int lane = t & 31;
    const int w    = t >> 5;
    const int qr   = lane >> 2;
    const int qc   = lane & 3;
    const int i0   = blockIdx.x * 256;
    const int nh   = blockIdx.y;
    const int n    = nh >> 3, h = nh & 7;

    qkvT += (size_t)n * LSEQ * QKV_CH;

    const int sr = t >> 2;
    const int sq = t & 3;

    auto stageKV = [&](int jt, int buf) {
        const __half* ksrc = qkvT + (size_t)(jt * 64 + sr) * QKV_CH + 512 + h * 64;
        const __half* vsrc = qkvT + (size_t)(jt * 64 + sr) * QKV_CH + 1024 + h * 64;
        uint32_t kdst = ksBase + (uint32_t)((buf * KS_HALFS + sr * KSW) * 2);
        uint32_t vdst = vsBase + (uint32_t)((buf * KS_HALFS + sr * KSW) * 2);
#pragma unroll
        for (int c = 0; c < 2; c++) {
            const int ch = sq + 4 * c;
            cp128(kdst + ch * 16, ksrc + ch * 8);
            cp128(vdst + ch * 16, vsrc + ch * 8);
        }
    };

    stageKV(0, 0); CP_COMMIT();
    {
        const __half* qsrc = qkvT + (size_t)(i0 + t) * QKV_CH + h * 64;
        uint32_t qdst = qsBase + (uint32_t)(t * QSW * 2);
#pragma unroll
        for (int c = 0; c < 8; c++)
            cp128(qdst + c * 16, qsrc + c * 8);
    }
    CP_COMMIT();
    CP_WAIT(0);
    __syncthreads();

    uint32_t qf[2][4][4];
    {
        const __half2 qs2 = __floats2half2_rn(QSCALE, QSCALE);
#pragma unroll
        for (int mf = 0; mf < 2; mf++)
#pragma unroll
            for (int kk = 0; kk < 4; kk++) {
                const int row = w * 32 + mf * 16 + (lane & 15);
                const int col = kk * 16 + (lane >> 4) * 8;
                ldsm4(qf[mf][kk], qsBase + (uint32_t)((row * QSW + col) * 2));
#pragma unroll
                for (int r = 0; r < 4; r++) {
                    __half2 v = __hmul2(*(__half2*)&qf[mf][kk][r], qs2);
                    qf[mf][kk][r] = *(uint32_t*)&v;
                }
            }
    }

    float lsum[2][2] = {{0.0f, 0.0f}, {0.0f, 0.0f}};
    float o[2][8][4];
#pragma unroll
    for (int mf = 0; mf < 2; mf++)
#pragma unroll
        for (int df = 0; df < 8; df++)
#pragma unroll
            for (int r = 0; r < 4; r++) o[mf][df][r] = 0.0f;

    const int njt = LSEQ / 64;
    for (int jt = 0; jt < njt; jt++) {
        const int s = jt & 1;
        if (jt + 1 < njt) { stageKV(jt + 1, s ^ 1); CP_COMMIT(); CP_WAIT(1); }
        else { CP_WAIT(0); }
        __syncthreads();

        float sreg[2][8][4];
#pragma unroll
        for (int mf = 0; mf < 2; mf++)
#pragma unroll
            for (int nf = 0; nf < 8; nf++)
#pragma unroll
                for (int r = 0; r < 4; r++) sreg[mf][nf][r] = 0.0f;

#pragma unroll
        for (int kk = 0; kk < 4; kk++) {
            const int bcol = kk * 16 + ((lane >> 3) & 1) * 8;
            uint32_t bf[8][2];
#pragma unroll
            for (int np = 0; np < 4; np++) {
                uint32_t r[4];
                const int row = np * 16 + ((lane >> 4) << 3) + (lane & 7);
                ldsm4(r, ksBase + (uint32_t)((s * KS_HALFS + row * KSW + bcol) * 2));
                bf[2 * np][0] = r[0]; bf[2 * np][1] = r[1];
                bf[2 * np + 1][0] = r[2]; bf[2 * np + 1][1] = r[3];
            }
#pragma unroll
            for (int nf = 0; nf < 8; nf++) {
                mma_f16(sreg[0][nf], qf[0][kk][0], qf[0][kk][1], qf[0][kk][2], qf[0][kk][3],
                        bf[nf][0], bf[nf][1]);
                mma_f16(sreg[1][nf], qf[1][kk][0], qf[1][kk][1], qf[1][kk][2], qf[1][kk][3],
                        bf[nf][0], bf[nf][1]);
            }
        }

        uint32_t pf[2][4][4];
#pragma unroll
        for (int mf = 0; mf < 2; mf++) {
#pragma unroll
            for (int nf = 0; nf < 8; nf++) {
                float p0 = ex2(sreg[mf][nf][0]);
                float p1 = ex2(sreg[mf][nf][1]);
                float p2 = ex2(sreg[mf][nf][2]);
                float p3 = ex2(sreg[mf][nf][3]);
                lsum[mf][0] += p0 + p1;
                lsum[mf][1] += p2 + p3;
                sreg[mf][nf][0] = p0; sreg[mf][nf][1] = p1;
                sreg[mf][nf][2] = p2; sreg[mf][nf][3] = p3;
            }
#pragma unroll
            for (int kk = 0; kk < 4; kk++) {
                pf[mf][kk][0] = h2pack(sreg[mf][2 * kk][0],     sreg[mf][2 * kk][1]);
                pf[mf][kk][1] = h2pack(sreg[mf][2 * kk][2],     sreg[mf][2 * kk][3]);
                pf[mf][kk][2] = h2pack(sreg[mf][2 * kk + 1][0], sreg[mf][2 * kk + 1][1]);
                pf[mf][kk][3] = h2pack(sreg[mf][2 * kk + 1][2], sreg[mf][2 * kk + 1][3]);
            }
        }

#pragma unroll
        for (int kk = 0; kk < 4; kk++) {
            uint32_t vf[8][2];
#pragma unroll
            for (int dp = 0; dp < 4; dp++) {
                uint32_t r[4];
                const int row = kk * 16 + (lane & 15);
                const int col = dp * 16 + (lane >> 4) * 8;
                ldsm4t(r, vsBase + (uint32_t)((s * KS_HALFS + row * KSW + col) * 2));
                vf[2 * dp][0] = r[0]; vf[2 * dp][1] = r[1];
                vf[2 * dp + 1][0] = r[2]; vf[2 * dp + 1][1] = r[3];
            }
#pragma unroll
            for (int df = 0; df < 8; df++) {
                mma_f16(o[0][df], pf[0][kk][0], pf[0][kk][1], pf[0][kk][2], pf[0][kk][3],
                        vf[df][0], vf[df][1]);
                mma_f16(o[1][df], pf[1][kk][0], pf[1][kk][1], pf[1][kk][2], pf[1][kk][3],
                        vf[df][0], vf[df][1]);
            }
        }
        __syncthreads();
    }

    // epilogue -> attsw[slab=h][m][swizzled chunk]
#pragma unroll
    for (int mf = 0; mf < 2; mf++) {
        float r0 = lsum[mf][0], r1 = lsum[mf][1];
        r0 += __shfl_xor_sync(0xffffffffu, r0, 1);
        r0 += __shfl_xor_sync(0xffffffffu, r0, 2);
        r1 += __shfl_xor_sync(0xffffffffu, r1, 1);
        r1 += __shfl_xor_sync(0xffffffffu, r1, 2);
        const float inv0 = 1.0f / r0, inv1 = 1.0f / r1;
        const int m0 = n * LSEQ + i0 + w * 32 + mf * 16 + qr;   // and m0+8
        __half* dst = attsw + (size_t)h * MROWS * 64;
#pragma unroll
        for (int df = 0; df < 8; df++) {
            const int off = ((df ^ (m0 & 7)) << 3) + qc * 2;
            *(uint32_t*)(dst + (size_t)m0 * 64 + off) =
                h2pack(o[mf][df][0] * inv0, o[mf][df][1] * inv0);
            *(uint32_t*)(dst + (size_t)(m0 + 8) * 64 + off) =
                h2pack(o[mf][df][2] * inv1, o[mf][df][3] * inv1);
        }
    }
}

// ---------------------------------------------------------------------------
// Launch
// ---------------------------------------------------------------------------
extern "C" void kernel_launch(void* const* d_in, const int* in_sizes, int n_in,
                              void* d_out, int out_size)
{
    const float* x     = (const float*)d_in[0];
    const float* w_qkv = (const float*)d_in[1];
    const float* w_out = (const float*)d_in[2];
    const float* b_out = (const float*)d_in[3];
    float* out = (float*)d_out;

    __half *xsw, *wqsw, *wosw, *qkvT, *attsw;
    cudaGetSymbolAddress((void**)&xsw,   g_xsw);
    cudaGetSymbolAddress((void**)&wqsw,  g_wqsw);
    cudaGetSymbolAddress((void**)&wosw,  g_wosw);
    cudaGetSymbolAddress((void**)&qkvT,  g_qkvT);
    cudaGetSymbolAddress((void**)&attsw, g_attsw);

    cudaFuncSetAttribute(gemm_qkv,  cudaFuncAttributeMaxDynamicSharedMemorySize, QKV_SMEM);
    cudaFuncSetAttribute(gemm_proj, cudaFuncAttributeMaxDynamicSharedMemorySize, QKV_SMEM);
    cudaFuncSetAttribute(flash_h,   cudaFuncAttributeMaxDynamicSharedMemorySize, FL_SMEM);

    // prep (vectorized)
    x_to_slabsw<<<dim3(LSEQ / 32, CH / 64, NB), 256>>>(x, xsw);
    w_to_slabsw<<<(QKV_CH * 64 + 255) / 256, 256>>>(w_qkv, wqsw, QKV_CH);
    w_to_slabsw<<<(CH * 64 + 255) / 256, 256>>>(w_out, wosw, CH);

    // 1) qkvT[(n,l)][o]  (bulk-staged GEMM)
    {
        dim3 grid(QKV_CH / 128, MROWS / 256);
        gemm_qkv<<<grid, 256, QKV_SMEM>>>(xsw, wqsw, qkvT);
    }
    // 2) flash attention -> attsw slab-major SW128
    {
        dim3 grid(LSEQ / 256, NB * NHEADS);
        flash_h<<<grid, 256, FL_SMEM>>>(qkvT, attsw);
    }
    // 3) out[n][o][l]  (bulk-staged GEMM)
    {
        dim3 grid(LSEQ / 128, CH / 256, NB);
        gemm_proj<<<grid, 256, QKV_SMEM>>>(wosw, attsw, out, b_out);
    }
}

// round 14
// speedup vs baseline: 1.8376x; 1.0888x over previous
#include <cuda_runtime.h>
#include <cuda_fp16.h>
#include <math.h>
#include <stdint.h>

#define NB     4
#define CH     512
#define LSEQ   2048
#define NHEADS 8
#define DHEAD  64
#define QKV_CH 1536
#define MROWS  (NB * LSEQ)          // 8192 flattened rows
#define NHTOT  (NB * NHEADS)        // 32
#define QSCALE 0.18033688f          /* 0.125 * log2(e) */
#define ONES_H2 0x3C003C00u

// ---------------------------------------------------------------------------
// Scratch (no cudaMalloc allowed)
// ---------------------------------------------------------------------------
__device__ __half g_xsw  [(size_t)8 * MROWS * 64];      // x slab-major SW128
__device__ __half g_wqsw [(size_t)8 * QKV_CH * 64];     // w_qkv slab-major SW128
__device__ __half g_wosw [(size_t)8 * CH * 64];         // w_out slab-major SW128
__device__ __half g_qsw  [(size_t)NHTOT * LSEQ * 64];   // q per-(n,h) SW128
__device__ __half g_ksw  [(size_t)NHTOT * LSEQ * 64];   // k per-(n,h) SW128
__device__ __half g_vsw  [(size_t)NHTOT * LSEQ * 64];   // v per-(n,h) SW128
__device__ __half g_attsw[(size_t)8 * MROWS * 64];      // att slab-major SW128 (slab=h)

// ---------------------------------------------------------------------------
// helpers
// ---------------------------------------------------------------------------
__device__ __forceinline__ uint32_t ex2h2(uint32_t x) {
    uint32_t r; asm("ex2.approx.f16x2 %0, %1;" : "=r"(r) : "r"(x)); return r;
}
__device__ __forceinline__ uint32_t h2pack(float x, float y) {
    __half2 h = __floats2half2_rn(x, y);
    return *(uint32_t*)&h;
}
__device__ __forceinline__ void mma_f16(float c[4],
    uint32_t a0, uint32_t a1, uint32_t a2, uint32_t a3,
    uint32_t b0, uint32_t b1)
{
    asm volatile(
        "mma.sync.aligned.m16n8k16.row.col.f32.f16.f16.f32 "
        "{%0,%1,%2,%3}, {%4,%5,%6,%7}, {%8,%9}, {%0,%1,%2,%3};"
        : "+f"(c[0]), "+f"(c[1]), "+f"(c[2]), "+f"(c[3])
        : "r"(a0), "r"(a1), "r"(a2), "r"(a3), "r"(b0), "r"(b1));
}
__device__ __forceinline__ void ldsm4(uint32_t r[4], uint32_t addr) {
    asm volatile("ldmatrix.sync.aligned.m8n8.x4.shared.b16 {%0,%1,%2,%3}, [%4];"
        : "=r"(r[0]), "=r"(r[1]), "=r"(r[2]), "=r"(r[3]) : "r"(addr));
}
__device__ __forceinline__ void ldsm4t(uint32_t r[4], uint32_t addr) {
    asm volatile("ldmatrix.sync.aligned.m8n8.x4.trans.shared.b16 {%0,%1,%2,%3}, [%4];"
        : "=r"(r[0]), "=r"(r[1]), "=r"(r[2]), "=r"(r[3]) : "r"(addr));
}
__device__ __forceinline__ void bulk_g2s(uint32_t dst, const void* src,
                                         uint32_t bytes, uint32_t mbar)
{
    asm volatile(
        "cp.async.bulk.shared::cluster.global.mbarrier::complete_tx::bytes "
        "[%0], [%1], %2, [%3];"
        :: "r"(dst), "l"(src), "r"(bytes), "r"(mbar) : "memory");
}
__device__ __forceinline__ void mbar_init(uint32_t mbar) {
    asm volatile("mbarrier.init.shared.b64 [%0], %1;" :: "r"(mbar), "r"(1u) : "memory");
}
__device__ __forceinline__ void mbar_expect(uint32_t mbar, uint32_t bytes) {
    asm volatile("mbarrier.arrive.expect_tx.shared.b64 _, [%0], %1;"
                 :: "r"(mbar), "r"(bytes) : "memory");
}
__device__ __forceinline__ void mbar_wait(uint32_t mbar, uint32_t parity) {
    asm volatile(
        "{\n\t.reg .pred P;\n\t"
        "LAB%=:\n\t"
        "mbarrier.try_wait.parity.acquire.cta.shared::cta.b64 P, [%0], %1;\n\t"
        "@!P bra LAB%=;\n\t"
        "}"
        :: "r"(mbar), "r"(parity) : "memory");
}

// ---------------------------------------------------------------------------
// prep (vectorized, round-13)
// ---------------------------------------------------------------------------
__global__ void x_to_slabsw(const float* __restrict__ in, __half* __restrict__ out)
{
    __shared__ float tile[64][33];
    const int n  = blockIdx.z;
    const int c0 = blockIdx.y * 64;
    const int l0 = blockIdx.x * 32;
    const int t  = threadIdx.x;

    const float* src = in + (size_t)n * CH * LSEQ;
    {
        const int lx = t & 31, cy = t >> 5;
#pragma unroll
        for (int j = 0; j < 8; j++)
            tile[cy * 8 + j][lx] = src[(size_t)(c0 + cy * 8 + j) * LSEQ + l0 + lx];
    }
    __syncthreads();
    {
        const int chunk = t & 7, l = t >> 3;
        const int m = n * LSEQ + l0 + l;
        __half h[8];
#pragma unroll
        for (int j = 0; j < 8; j++) h[j] = __float2half(tile[chunk * 8 + j][l]);
        const int slab = c0 >> 6;
        *(uint4*)&out[(size_t)slab * MROWS * 64 + (size_t)m * 64
                      + ((chunk ^ (m & 7)) << 3)] = *(uint4*)h;
    }
}

__global__ void w_to_slabsw(const float* __restrict__ in, __half* __restrict__ out, int M)
{
    const int idx = blockIdx.x * blockDim.x + threadIdx.x;
    if (idx >= M * 64) return;
    const int m = idx >> 6, kc = idx & 63;
    const int slab = kc >> 3, chunk = kc & 7;
    float4 f0 = *(const float4*)&in[(size_t)m * CH + kc * 8];
    float4 f1 = *(const float4*)&in[(size_t)m * CH + kc * 8 + 4];
    __half h[8];
    h[0] = __float2half(f0.x); h[1] = __float2half(f0.y);
    h[2] = __float2half(f0.z); h[3] = __float2half(f0.w);
    h[4] = __float2half(f1.x); h[5] = __float2half(f1.y);
    h[6] = __float2half(f1.z); h[7] = __float2half(f1.w);
    *(uint4*)&out[(size_t)slab * M * 64 + (size_t)m * 64
                  + ((chunk ^ (m & 7)) << 3)] = *(uint4*)h;
}

// ---------------------------------------------------------------------------
// QKV GEMM with bulk staging (round-12 mainloop); epilogue scatters q,k,v
// into per-(n,h) SW128 buffers [nh][2048][64].
// ---------------------------------------------------------------------------
#define QA_BYTES 32768
#define QB_BYTES 16384
#define QSTG     (QA_BYTES + QB_BYTES)
#define QKV_SMEM (1024 + 3 * QSTG)   // 148480

__global__ __launch_bounds__(256, 1)
void gemm_qkv(const __half* __restrict__ Asw, const __half* __restrict__ Wsw,
              __half* __restrict__ Qsw, __half* __restrict__ Ksw,
              __half* __restrict__ Vsw)
{
    extern __shared__ __half gsm[];
    const uint32_t base = (uint32_t)__cvta_generic_to_shared(gsm);

    const int t    = threadIdx.x;
    const int lane = t & 31;
    const int w    = t >> 5;
    const int qr   = lane >> 2;
    const int qc   = lane & 3;
    const int bm   = blockIdx.y * 256;
    const int bn   = blockIdx.x * 128;

    const int wm = (w >> 1) * 64;
    const int wn = (w & 1) * 64;

    if (t == 0) {
#pragma unroll
        for (int s = 0; s < 3; s++) mbar_init(base + s * 8);
    }
    __syncthreads();

    auto stage = [&](int slab, int buf) {
        const uint32_t mbar = base + buf * 8;
        const uint32_t aDst = base + 1024 + buf * QSTG;
        const uint32_t bDst = aDst + QA_BYTES;
        mbar_expect(mbar, QSTG);
        bulk_g2s(aDst, Asw + (size_t)slab * MROWS * 64 + (size_t)bm * 64,
                 QA_BYTES, mbar);
        bulk_g2s(bDst, Wsw + (size_t)slab * QKV_CH * 64 + (size_t)bn * 64,
                 QB_BYTES, mbar);
    };

    if (t == 0) { stage(0, 0); stage(1, 1); }

    float acc[4][8][4];
#pragma unroll
    for (int i = 0; i < 4; i++)
#pragma unroll
        for (int j = 0; j < 8; j++)
#pragma unroll
            for (int r = 0; r < 4; r++) acc[i][j][r] = 0.0f;

    const int nslabs = CH / 64;
    for (int i = 0; i < nslabs; i++) {
        __syncthreads();
        if (t == 0 && i + 2 < nslabs) stage(i + 2, (i + 2) % 3);
        mbar_wait(base + (i % 3) * 8, (uint32_t)((i / 3) & 1));

        const uint32_t aS = base + 1024 + (i % 3) * QSTG;
        const uint32_t bS = aS + QA_BYTES;

#pragma unroll
        for (int kk = 0; kk < 4; kk++) {
            const int chA = kk * 2 + (lane >> 4);
            const int chB = kk * 2 + ((lane >> 3) & 1);
            uint32_t af[4][4];
#pragma unroll
            for (int mf = 0; mf < 4; mf++) {
                const int mi = wm + mf * 16 + (lane & 15);
                ldsm4(af[mf], aS + (uint32_t)(mi * 128 + ((chA ^ (mi & 7)) << 4)));
            }
            uint32_t bf[8][2];
#pragma unroll
            for (int np = 0; np < 4; np++) {
                uint32_t r[4];
                const int rb = wn + np * 16 + ((lane >> 4) << 3) + (lane & 7);
                ldsm4(r, bS + (uint32_t)(rb * 128 + ((chB ^ (rb & 7)) << 4)));
                bf[2 * np][0] = r[0]; bf[2 * np][1] = r[1];
                bf[2 * np + 1][0] = r[2]; bf[2 * np + 1][1] = r[3];
            }
#pragma unroll
            for (int nf = 0; nf < 8; nf++)
#pragma unroll
                for (int mf = 0; mf < 4; mf++)
                    mma_f16(acc[mf][nf], af[mf][0], af[mf][1], af[mf][2], af[mf][3],
                            bf[nf][0], bf[nf][1]);
        }
    }

    // epilogue -> q/k/v per-(n,h) SW128 buffers
#pragma unroll
    for (int nf = 0; nf < 8; nf++) {
        const int o  = bn + wn + nf * 8;         // channel base (8-aligned)
        const int bi = o >> 9;                   // 0=q,1=k,2=v
        const int oc = o & 511;
        const int h  = oc >> 6;
        const int d0 = oc & 63;
        __half* dst = (bi == 0 ? Qsw : (bi == 1 ? Ksw : Vsw));
#pragma unroll
        for (int mf = 0; mf < 4; mf++) {
            const int row = bm + wm + mf * 16 + qr;   // global token m, and row+8
            const size_t rb = ((size_t)((row >> 11) * 8 + h) * LSEQ + (row & 2047)) * 64;
            const int off = (((d0 >> 3) ^ (row & 7)) << 3) + qc * 2;
            *(uint32_t*)(dst + rb + off) = h2pack(acc[mf][nf][0], acc[mf][nf][1]);
            *(uint32_t*)(dst + rb + 8 * 64 + off) = h2pack(acc[mf][nf][2], acc[mf][nf][3]);
        }
    }
}

// ---------------------------------------------------------------------------
// Projection GEMM with bulk staging (round-13, unchanged).
// ---------------------------------------------------------------------------
__global__ __launch_bounds__(256, 1)
void gemm_proj(const __half* __restrict__ Wsw, const __half* __restrict__ Bsw,
               float* __restrict__ out, const float* __restrict__ bias)
{
    extern __shared__ __half gsm[];
    const uint32_t base = (uint32_t)__cvta_generic_to_shared(gsm);

    const int t    = threadIdx.x;
    const int lane = t & 31;
    const int w    = t >> 5;
    const int qr   = lane >> 2;
    const int qc   = lane & 3;
    const int bm   = blockIdx.y * 256;
    const int bn   = blockIdx.x * 128;
    const int n    = blockIdx.z;
    const int brow = n * LSEQ + bn;

    const int wm = (w >> 1) * 64;
    const int wn = (w & 1) * 64;

    if (t == 0) {
#pragma unroll
        for (int s = 0; s < 3; s++) mbar_init(base + s * 8);
    }
    __syncthreads();

    auto stage = [&](int slab, int buf) {
        const uint32_t mbar = base + buf * 8;
        const uint32_t aDst = base + 1024 + buf * QSTG;
        const uint32_t bDst = aDst + QA_BYTES;
        mbar_expect(mbar, QSTG);
        bulk_g2s(aDst, Wsw + (size_t)slab * CH * 64 + (size_t)bm * 64,
                 QA_BYTES, mbar);
        bulk_g2s(bDst, Bsw + (size_t)slab * MROWS * 64 + (size_t)brow * 64,
                 QB_BYTES, mbar);
    };

    if (t == 0) { stage(0, 0); stage(1, 1); }

    float acc[4][8][4];
#pragma unroll
    for (int i = 0; i < 4; i++)
#pragma unroll
        for (int j = 0; j < 8; j++)
#pragma unroll
            for (int r = 0; r < 4; r++) acc[i][j][r] = 0.0f;

    const int nslabs = CH / 64;
    for (int i = 0; i < nslabs; i++) {
        __syncthreads();
        if (t == 0 && i + 2 < nslabs) stage(i + 2, (i + 2) % 3);
        mbar_wait(base + (i % 3) * 8, (uint32_t)((i / 3) & 1));

        const uint32_t aS = base + 1024 + (i % 3) * QSTG;
        const uint32_t bS = aS + QA_BYTES;

#pragma unroll
        for (int kk = 0; kk < 4; kk++) {
            const int chA = kk * 2 + (lane >> 4);
            const int chB = kk * 2 + ((lane >> 3) & 1);
            uint32_t af[4][4];
#pragma unroll
            for (int mf = 0; mf < 4; mf++) {
                const int mi = wm + mf * 16 + (lane & 15);
                ldsm4(af[mf], aS + (uint32_t)(mi * 128 + ((chA ^ (mi & 7)) << 4)));
            }
            uint32_t bf[8][2];
#pragma unroll
            for (int np = 0; np < 4; np++) {
                uint32_t r[4];
                const int rb = wn + np * 16 + ((lane >> 4) << 3) + (lane & 7);
                ldsm4(r, bS + (uint32_t)(rb * 128 + ((chB ^ (rb & 7)) << 4)));
                bf[2 * np][0] = r[0]; bf[2 * np][1] = r[1];
                bf[2 * np + 1][0] = r[2]; bf[2 * np + 1][1] = r[3];
            }
#pragma unroll
            for (int nf = 0; nf < 8; nf++)
#pragma unroll
                for (int mf = 0; mf < 4; mf++)
                    mma_f16(acc[mf][nf], af[mf][0], af[mf][1], af[mf][2], af[mf][3],
                            bf[nf][0], bf[nf][1]);
        }
    }

    out += (size_t)n * CH * LSEQ;
#pragma unroll
    for (int mf = 0; mf < 4; mf++) {
        const int row = bm + wm + mf * 16 + qr;
        const float bv0 = bias[row], bv1 = bias[row + 8];
#pragma unroll
        for (int nf = 0; nf < 8; nf++) {
            const int col = bn + wn + nf * 8 + qc * 2;
            *(float2*)(out + (size_t)row * LSEQ + col) =
                make_float2(acc[mf][nf][0] + bv0, acc[mf][nf][1] + bv0);
            *(float2*)(out + (size_t)(row + 8) * LSEQ + col) =
                make_float2(acc[mf][nf][2] + bv1, acc[mf][nf][3] + bv1);
        }
    }
}

// ---------------------------------------------------------------------------
// Flash v7: bulk-staged Q/K/V from per-(n,h) SW128 buffers; ex2.approx.f16x2
// softmax; row-sums via ones-fragment MMA (no shuffle reductions).
// Bq=256, 256 threads, 8 warps x m32n64, Bk=64.
// smem: [0..24) mbars (K/V buf0, buf1, Q), Q tile @1024 (32KB), K 2x8KB, V 2x8KB.
// ---------------------------------------------------------------------------
#define FLQ_BYTES 32768
#define FLK_BYTES 8192
#define FL_SMEM   (1024 + FLQ_BYTES + 4 * FLK_BYTES)   // 66560

__global__ __launch_bounds__(256, 1)
void flash_h(const __half* __restrict__ Qsw, const __half* __restrict__ Ksw,
             const __half* __restrict__ Vsw, __half* __restrict__ attsw)
{
    extern __shared__ __half fsm[];
    const uint32_t base   = (uint32_t)__cvta_generic_to_shared(fsm);
    const uint32_t qsBase = base + 1024;
    const uint32_t ksBase = qsBase + FLQ_BYTES;
    const uint32_t vsBase = ksBase + 2 * FLK_BYTES;

    const int t    = threadIdx.x;
    const int lane = t & 31;
    const int w    = t >> 5;
    const int qr   = lane >> 2;
    const int qc   = lane & 3;
    const int i0   = blockIdx.x * 256;
    const int nh   = blockIdx.y;
    const int n    = nh >> 3, h = nh & 7;

    const __half* qb = Qsw + (size_t)nh * LSEQ * 64;
    const __half* kb = Ksw + (size_t)nh * LSEQ * 64;
    const __half* vb = Vsw + (size_t)nh * LSEQ * 64;

    if (t == 0) { mbar_init(base); mbar_init(base + 8); mbar_init(base + 16); }
    __syncthreads();

    auto stageKV = [&](int jt, int buf) {
        const uint32_t mbar = base + buf * 8;
        mbar_expect(mbar, 2 * FLK_BYTES);
        bulk_g2s(ksBase + buf * FLK_BYTES, kb + (size_t)jt * 64 * 64, FLK_BYTES, mbar);
        bulk_g2s(vsBase + buf * FLK_BYTES, vb + (size_t)jt * 64 * 64, FLK_BYTES, mbar);
    };

    if (t == 0) {
        mbar_expect(base + 16, FLQ_BYTES);
        bulk_g2s(qsBase, qb + (size_t)i0 * 64, FLQ_BYTES, base + 16);
        stageKV(0, 0);
    }

    // Q fragments (scaled)
    uint32_t qf[2][4][4];
    mbar_wait(base + 16, 0);
    {
        const __half2 qs2 = __floats2half2_rn(QSCALE, QSCALE);
#pragma unroll
        for (int mf = 0; mf < 2; mf++)
#pragma unroll
            for (int kk = 0; kk < 4; kk++) {
                const int row = w * 32 + mf * 16 + (lane & 15);
                const int ch  = kk * 2 + (lane >> 4);
                ldsm4(qf[mf][kk], qsBase + (uint32_t)(row * 128 + ((ch ^ (row & 7)) << 4)));
#pragma unroll
                for (int r = 0; r < 4; r++) {
                    __half2 v = __hmul2(*(__half2*)&qf[mf][kk][r], qs2);
                    qf[mf][kk][r] = *(uint32_t*)&v;
                }
            }
    }

    float lacc[2][4] = {{0, 0, 0, 0}, {0, 0, 0, 0}};
    float o[2][8][4];
#pragma unroll
    for (int mf = 0; mf < 2; mf++)
#pragma unroll
        for (int df = 0; df < 8; df++)
#pragma unroll
            for (int r = 0; r < 4; r++) o[mf][df][r] = 0.0f;

    const int njt = LSEQ / 64;
    for (int jt = 0; jt < njt; jt++) {
        const int s = jt & 1;
        __syncthreads();                 // all readers done with buffer s (older fill)
        if (t == 0 && jt + 1 < njt) stageKV(jt + 1, s ^ 1);
        mbar_wait(base + s * 8, (uint32_t)((jt >> 1) & 1));

        const uint32_t kS = ksBase + s * FLK_BYTES;
        const uint32_t vS = vsBase + s * FLK_BYTES;

        // ---- S = Q K^T ----
        float sreg[2][8][4];
#pragma unroll
        for (int mf = 0; mf < 2; mf++)
#pragma unroll
            for (int nf = 0; nf < 8; nf++)
#pragma unroll
                for (int r = 0; r < 4; r++) sreg[mf][nf][r] = 0.0f;

#pragma unroll
        for (int kk = 0; kk < 4; kk++) {
            const int chB = kk * 2 + ((lane >> 3) & 1);
            uint32_t bf[8][2];
#pragma unroll
            for (int np = 0; np < 4; np++) {
                uint32_t r[4];
                const int rb = np * 16 + ((lane >> 4) << 3) + (lane & 7);
                ldsm4(r, kS + (uint32_t)(rb * 128 + ((chB ^ (rb & 7)) << 4)));
                bf[2 * np][0] = r[0]; bf[2 * np][1] = r[1];
                bf[2 * np + 1][0] = r[2]; bf[2 * np + 1][1] = r[3];
            }
#pragma unroll
            for (int nf = 0; nf < 8; nf++) {
                mma_f16(sreg[0][nf], qf[0][kk][0], qf[0][kk][1], qf[0][kk][2], qf[0][kk][3],
                        bf[nf][0], bf[nf][1]);
                mma_f16(sreg[1][nf], qf[1][kk][0], qf[1][kk][1], qf[1][kk][2], qf[1][kk][3],
                        bf[nf][0], bf[nf][1]);
            }
        }

        // ---- P = 2^S in fp16x2 (fused exp+pack); lsum via ones MMA ----
        uint32_t pf[2][4][4];
#pragma unroll
        for (int mf = 0; mf < 2; mf++) {
#pragma unroll
            for (int kk = 0; kk < 4; kk++) {
                pf[mf][kk][0] = ex2h2(h2pack(sreg[mf][2 * kk][0],     sreg[mf][2 * kk][1]));
                pf[mf][kk][1] = ex2h2(h2pack(sreg[mf][2 * kk][2],     sreg[mf][2 * kk][3]));
                pf[mf][kk][2] = ex2h2(h2pack(sreg[mf][2 * kk + 1][0], sreg[mf][2 * kk + 1][1]));
                pf[mf][kk][3] = ex2h2(h2pack(sreg[mf][2 * kk + 1][2], sreg[mf][2 * kk + 1][3]));
            }
#pragma unroll
            for (int kk = 0; kk < 4; kk++)
                mma_f16(lacc[mf], pf[mf][kk][0], pf[mf][kk][1], pf[mf][kk][2], pf[mf][kk][3],
                        ONES_H2, ONES_H2);
        }

        // ---- O += P @ V ----
#pragma unroll
        for (int kk = 0; kk < 4; kk++) {
            uint32_t vf[8][2];
#pragma unroll
            for (int dp = 0; dp < 4; dp++) {
                uint32_t r[4];
                const int row = kk * 16 + (lane & 15);
                const int ch  = dp * 2 + (lane >> 4);
                ldsm4t(r, vS + (uint32_t)(row * 128 + ((ch ^ (row & 7)) << 4)));
                vf[2 * dp][0] = r[0]; vf[2 * dp][1] = r[1];
                vf[2 * dp + 1][0] = r[2]; vf[2 * dp + 1][1] = r[3];
            }
#pragma unroll
            for (int df = 0; df < 8; df++) {
                mma_f16(o[0][df], pf[0][kk][0], pf[0][kk][1], pf[0][kk][2], pf[0][kk][3],
                        vf[df][0], vf[df][1]);
                mma_f16(o[1][df], pf[1][kk][0], pf[1][kk][1], pf[1][kk][2], pf[1][kk][3],
                        vf[df][0], vf[df][1]);
            }
        }
    }

    // epilogue -> attsw[slab=h][m][swizzled chunk]; lsum from lacc (no shuffles)
#pragma unroll
    for (int mf = 0; mf < 2; mf++) {
        const float inv0 = 1.0f / lacc[mf][0];
        const float inv1 = 1.0f / lacc[mf][2];
        const int m0 = n * LSEQ + i0 + w * 32 + mf * 16 + qr;
        __half* dst = attsw + (size_t)h * MROWS * 64;
#pragma unroll
        for (int df = 0; df < 8; df++) {
            const int off = ((df ^ (m0 & 7)) << 3) + qc * 2;
            *(uint32_t*)(dst + (size_t)m0 * 64 + off) =
                h2pack(o[mf][df][0] * inv0, o[mf][df][1] * inv0);
            *(uint32_t*)(dst + (size_t)(m0 + 8) * 64 + off) =
                h2pack(o[mf][df][2] * inv1, o[mf][df][3] * inv1);
        }
    }
}

// ---------------------------------------------------------------------------
// Launch
// ---------------------------------------------------------------------------
extern "C" void kernel_launch(void* const* d_in, const int* in_sizes, int n_in,
                              void* d_out, int out_size)
{
    const float* x     = (const float*)d_in[0];
    const float* w_qkv = (const float*)d_in[1];
    const float* w_out = (const float*)d_in[2];
    const float* b_out = (const float*)d_in[3];
    float* out = (float*)d_out;

    __half *xsw, *wqsw, *wosw, *qsw, *ksw, *vsw, *attsw;
    cudaGetSymbolAddress((void**)&xsw,   g_xsw);
    cudaGetSymbolAddress((void**)&wqsw,  g_wqsw);
    cudaGetSymbolAddress((void**)&wosw,  g_wosw);
    cudaGetSymbolAddress((void**)&qsw,   g_qsw);
    cudaGetSymbolAddress((void**)&ksw,   g_ksw);
    cudaGetSymbolAddress((void**)&vsw,   g_vsw);
    cudaGetSymbolAddress((void**)&attsw, g_attsw);

    cudaFuncSetAttribute(gemm_qkv,  cudaFuncAttributeMaxDynamicSharedMemorySize, QKV_SMEM);
    cudaFuncSetAttribute(gemm_proj, cudaFuncAttributeMaxDynamicSharedMemorySize, QKV_SMEM);
    cudaFuncSetAttribute(flash_h,   cudaFuncAttributeMaxDynamicSharedMemorySize, FL_SMEM);

    // prep
    x_to_slabsw<<<dim3(LSEQ / 32, CH / 64, NB), 256>>>(x, xsw);
    w_to_slabsw<<<(QKV_CH * 64 + 255) / 256, 256>>>(w_qkv, wqsw, QKV_CH);
    w_to_slabsw<<<(CH * 64 + 255) / 256, 256>>>(w_out, wosw, CH);

    // 1) QKV projection -> per-(n,h) SW128 q/k/v buffers
    {
        dim3 grid(QKV_CH / 128, MROWS / 256);
        gemm_qkv<<<grid, 256, QKV_SMEM>>>(xsw, wqsw, qsw, ksw, vsw);
    }
    // 2) flash attention -> attsw slab-major SW128
    {
        dim3 grid(LSEQ / 256, NHTOT);
        flash_h<<<grid, 256, FL_SMEM>>>(qsw, ksw, vsw, attsw);
    }
    // 3) out[n][o][l]  (bulk-staged GEMM)
    {
        dim3 grid(LSEQ / 128, CH / 256, NB);
        gemm_proj<<<grid, 256, QKV_SMEM>>>(wosw, attsw, out, b_out);
    }
}